// round 14
// baseline (speedup 1.0000x reference)
#include <cuda_runtime.h>
#include <cuda_fp16.h>
#include <mma.h>
#include <math.h>

using namespace nvcuda;

// Problem constants (fixed shapes)
#define NN 4096
#define DD 256
#define NW 128          // adjacency words per row (4096/32)
#define MAXD 512        // max neighbors kept (avg ~64 for random E=131072 graph)

// -------- static device scratch --------
__device__ unsigned g_adj[NN * NW];        // 2 MB bitmask adjacency
__device__ int      g_deg[NN];
__device__ int      g_nbr[NN * MAXD];      // 8 MB compact neighbor lists (pre-scaled *512)
__device__ float    g_q  [NN * DD];        // 4 MB  (q, fp32)
__device__ uint4    g_kvh_raw[NN * 64];    // 4 MB  (k,v as fp16: 512 halves/node)
__device__ float    g_ctx[NN * DD];        // 4 MB
__device__ float    g_x  [NN * DD];        // 4 MB
__device__ float    g_y  [NN * DD];        // 4 MB

// -------- scatter edges (symmetric, no self loops, dedup via OR); edge_index is int32 --------
__global__ void build_adj_kernel(const int* __restrict__ ei, int ne) {
    int e = blockIdx.x * blockDim.x + threadIdx.x;
    if (e >= ne) return;
    int s = ei[e];
    int d = ei[ne + e];
    if (s == d) return;
    if ((unsigned)s >= NN || (unsigned)d >= NN) return;
    atomicOr(&g_adj[s * NW + (d >> 5)], 1u << (d & 31));
    atomicOr(&g_adj[d * NW + (s >> 5)], 1u << (s & 31));
}

// -------- warp-per-row compaction (deterministic, sorted); re-zeroes g_adj for replay --------
__global__ __launch_bounds__(256) void compact_kernel() {
    int n = blockIdx.x * 8 + (threadIdx.x >> 5);
    int lane = threadIdx.x & 31;

    uint4 wv = *(uint4*)&g_adj[n * NW + lane * 4];
    *(uint4*)&g_adj[n * NW + lane * 4] = make_uint4(0u, 0u, 0u, 0u);  // reset for replay

    int c = __popc(wv.x) + __popc(wv.y) + __popc(wv.z) + __popc(wv.w);
    int x = c;
#pragma unroll
    for (int o = 1; o < 32; o <<= 1) {
        int y = __shfl_up_sync(0xffffffffu, x, o);
        if (lane >= o) x += y;
    }
    int total = __shfl_sync(0xffffffffu, x, 31);
    int base = x - c;                       // exclusive prefix

    int* dst = g_nbr + (size_t)n * MAXD;
    unsigned ws[4] = {wv.x, wv.y, wv.z, wv.w};
#pragma unroll
    for (int u = 0; u < 4; u++) {
        unsigned bits = ws[u];
        int boff = (lane * 4 + u) * 32;
        while (bits) {
            int b = __ffs(bits) - 1;
            bits &= bits - 1;
            if (base < MAXD) dst[base] = (boff + b) * 512;   // pre-scaled element offset
            base++;
        }
    }
    if (lane == 31) g_deg[n] = (total < MAXD) ? total : MAXD;
}

// ======== tf32 wmma GEMM: C[M,Nc] = A[M,K] @ B[Nc,K]^T + bias ========
// BM=64, BN=64, BK=16, 128 threads (4 warps 2x2, warp tile 32x32 = 2x2 m16n16k8),
// double-buffered smem, tf32 RN at smem store, smem-staged epilogue.
// ASEL: 0 = emb, 1 = g_ctx, 2 = g_x
// CSEL: 0 = qkv split output (q fp32 / kv fp16), 1 = g_x (+SELECT), 2 = g_y
#define BM 64
#define BN 64
#define GBK 16
#define BKP 20
#define GNT 128

struct GemmSmem {
    union {
        struct {
            float As[2][BM][BKP];   // 10240 B
            float Bs[2][BN][BKP];   // 10240 B
        } p;
        float stage[4][32][36];     // 18432 B (epilogue staging)
    };
};

template<int ASEL, int CSEL, bool SELECT>
__global__ __launch_bounds__(GNT) void gemm_kernel(const float* __restrict__ emb,
                                                   const float* __restrict__ B,
                                                   const float* __restrict__ bias,
                                                   int Nc) {
    const float* A = (ASEL == 0) ? emb : (ASEL == 1 ? (const float*)g_ctx : (const float*)g_x);
    const int K = DD;

    __shared__ GemmSmem sm;

    const int tid = threadIdx.x;
    const int w = tid >> 5, lane = tid & 31;
    const int wy = w >> 1, wx = w & 1;          // warp grid 2x2
    const int row0 = blockIdx.y * BM;
    const int col0 = blockIdx.x * BN;

    float4 ra[2], rb[2];
    auto gload = [&](int k0) {
#pragma unroll
        for (int u = 0; u < 2; u++) {
            int i = tid + u * GNT;
            int r = i >> 2, kk = (i & 3) * 4;
            ra[u] = *(const float4*)(A + (size_t)(row0 + r) * K + k0 + kk);
            rb[u] = *(const float4*)(B + (size_t)(col0 + r) * K + k0 + kk);
        }
    };
    auto sstore = [&](int buf) {
#pragma unroll
        for (int u = 0; u < 2; u++) {
            int i = tid + u * GNT;
            int r = i >> 2, kk = (i & 3) * 4;
            sm.p.As[buf][r][kk + 0] = wmma::__float_to_tf32(ra[u].x);
            sm.p.As[buf][r][kk + 1] = wmma::__float_to_tf32(ra[u].y);
            sm.p.As[buf][r][kk + 2] = wmma::__float_to_tf32(ra[u].z);
            sm.p.As[buf][r][kk + 3] = wmma::__float_to_tf32(ra[u].w);
            sm.p.Bs[buf][r][kk + 0] = wmma::__float_to_tf32(rb[u].x);
            sm.p.Bs[buf][r][kk + 1] = wmma::__float_to_tf32(rb[u].y);
            sm.p.Bs[buf][r][kk + 2] = wmma::__float_to_tf32(rb[u].z);
            sm.p.Bs[buf][r][kk + 3] = wmma::__float_to_tf32(rb[u].w);
        }
    };

    wmma::fragment<wmma::accumulator, 16, 16, 8, float> cf[2][2];
#pragma unroll
    for (int i = 0; i < 2; i++)
#pragma unroll
        for (int j = 0; j < 2; j++)
            wmma::fill_fragment(cf[i][j], 0.0f);

    gload(0);
    sstore(0);
    __syncthreads();

    const int KT = K / GBK;
    for (int kt = 0; kt < KT; kt++) {
        int buf = kt & 1;
        if (kt + 1 < KT) gload((kt + 1) * GBK);
#pragma unroll
        for (int ks = 0; ks < GBK; ks += 8) {
            wmma::fragment<wmma::matrix_a, 16, 16, 8, wmma::precision::tf32, wmma::row_major> af[2];
            wmma::fragment<wmma::matrix_b, 16, 16, 8, wmma::precision::tf32, wmma::col_major> bf[2];
#pragma unroll
            for (int i = 0; i < 2; i++)
                wmma::load_matrix_sync(af[i], &sm.p.As[buf][wy * 32 + i * 16][ks], BKP);
#pragma unroll
            for (int j = 0; j < 2; j++)
                wmma::load_matrix_sync(bf[j], &sm.p.Bs[buf][wx * 32 + j * 16][ks], BKP);
#pragma unroll
            for (int i = 0; i < 2; i++)
#pragma unroll
                for (int j = 0; j < 2; j++)
                    wmma::mma_sync(cf[i][j], af[i], bf[j], cf[i][j]);
        }
        if (kt + 1 < KT) {
            sstore(buf ^ 1);
            __syncthreads();
        }
    }

    // epilogue: stage accumulators to smem, add bias, route to destination
    __syncthreads();
#pragma unroll
    for (int i = 0; i < 2; i++)
#pragma unroll
        for (int j = 0; j < 2; j++)
            wmma::store_matrix_sync(&sm.stage[w][i * 16][j * 16], cf[i][j], 36, wmma::mem_row_major);
    __syncwarp();

    {
        int r = row0 + wy * 32 + lane;
        int cbase = col0 + wx * 32;
        bool alt = SELECT && (g_deg[r] == 0);
#pragma unroll
        for (int j = 0; j < 8; j++) {
            int cc = cbase + j * 4;
            float4 bv = *(const float4*)(bias + cc);
            float4 v;
            v.x = sm.stage[w][lane][j * 4 + 0] + bv.x;
            v.y = sm.stage[w][lane][j * 4 + 1] + bv.y;
            v.z = sm.stage[w][lane][j * 4 + 2] + bv.z;
            v.w = sm.stage[w][lane][j * 4 + 3] + bv.w;
            if (CSEL == 0) {
                if (cbase < 256) {                       // q -> fp32
                    *(float4*)(g_q + (size_t)r * DD + cc) = v;
                } else {                                 // k,v -> fp16
                    __half2 h01 = __floats2half2_rn(v.x, v.y);
                    __half2 h23 = __floats2half2_rn(v.z, v.w);
                    uint2 hv;
                    hv.x = *(unsigned*)&h01;
                    hv.y = *(unsigned*)&h23;
                    *(uint2*)((__half*)g_kvh_raw + (size_t)r * 512 + (cc - 256)) = hv;
                }
            } else {
                float* C = (CSEL == 1) ? g_x : g_y;
                if (SELECT && alt) v = *(const float4*)(emb + (size_t)r * DD + cc);
                *(float4*)(C + (size_t)r * Nc + cc) = v;
            }
        }
    }
}

// ======== sparse attention (fp16 k/v): 4-lane dot groups, 16 neighbors per warp-iter ========
// R11 configuration (best measured): block = node, 8 warps = 8 heads, smem-staged
// neighbor list, fp32 score dot, MLP=4. Lane: group g = lane>>2 (neighbor slot 0..7),
// d8 = (lane&3)*8. No online max (scores ~N(0,0.1)); exp clamp 80; exp(-inf)=0 tail.
__global__ __launch_bounds__(256) void attn_kernel() {
    __shared__ int snbr[MAXD];
    __shared__ int sdeg;
    int n = blockIdx.x, tid = threadIdx.x;
    int w = tid >> 5, lane = tid & 31;
    int g = lane >> 2, d8 = (lane & 3) * 8;
    if (tid == 0) sdeg = g_deg[n];
    __syncthreads();
    int dg = sdeg;
    for (int i = tid; i < dg; i += 256)
        snbr[i] = g_nbr[(size_t)n * MAXD + i];   // already pre-scaled *512
    __syncthreads();

    const int woff = w * 32 + d8;

    if (dg == 0) {
        if (lane < 4) {
            *(float4*)&g_ctx[(size_t)n * DD + woff]     = make_float4(0.f, 0.f, 0.f, 0.f);
            *(float4*)&g_ctx[(size_t)n * DD + woff + 4] = make_float4(0.f, 0.f, 0.f, 0.f);
        }
        return;
    }

    float q8[8];
    *(float4*)&q8[0] = *(const float4*)(g_q + (size_t)n * DD + woff);
    *(float4*)&q8[4] = *(const float4*)(g_q + (size_t)n * DD + woff + 4);

    const float sc = 0.17677669529663687f;    // 1/sqrt(32)
    float s = 0.f;
    float acc[8] = {};
    const __half* kvh = (const __half*)g_kvh_raw;

    for (int i = 0; i < dg; i += 16) {
        int idx0 = i + g, idx1 = i + 8 + g;
        bool va = idx0 < dg, vb = idx1 < dg;
        const __half* pa = kvh + snbr[va ? idx0 : i] + woff;
        const __half* pb = kvh + snbr[vb ? idx1 : i] + woff;
        uint4 ka = *(const uint4*)pa;
        uint4 kb = *(const uint4*)pb;
        uint4 vaa = *(const uint4*)(pa + 256);
        uint4 vbb = *(const uint4*)(pb + 256);

        float2 a0 = __half22float2(*(__half2*)&ka.x);
        float2 a1 = __half22float2(*(__half2*)&ka.y);
        float2 a2 = __half22float2(*(__half2*)&ka.z);
        float2 a3 = __half22float2(*(__half2*)&ka.w);
        float2 b0 = __half22float2(*(__half2*)&kb.x);
        float2 b1 = __half22float2(*(__half2*)&kb.y);
        float2 b2 = __half22float2(*(__half2*)&kb.z);
        float2 b3 = __half22float2(*(__half2*)&kb.w);

        float p0 = q8[0] * a0.x + q8[1] * a0.y + q8[2] * a1.x + q8[3] * a1.y
                 + q8[4] * a2.x + q8[5] * a2.y + q8[6] * a3.x + q8[7] * a3.y;
        float p1 = q8[0] * b0.x + q8[1] * b0.y + q8[2] * b1.x + q8[3] * b1.y
                 + q8[4] * b2.x + q8[5] * b2.y + q8[6] * b3.x + q8[7] * b3.y;
        p0 += __shfl_xor_sync(0xffffffffu, p0, 1);
        p1 += __shfl_xor_sync(0xffffffffu, p1, 1);
        p0 += __shfl_xor_sync(0xffffffffu, p0, 2);
        p1 += __shfl_xor_sync(0xffffffffu, p1, 2);
        p0 = va ? fminf(p0 * sc, 80.f) : -INFINITY;
        p1 = vb ? fminf(p1 * sc, 80.f) : -INFINITY;
        float e0 = __expf(p0);
        float e1 = __expf(p1);
        s += e0 + e1;

        float2 w0 = __half22float2(*(__half2*)&vaa.x);
        float2 w1 = __half22float2(*(__half2*)&vaa.y);
        float2 w2 = __half22float2(*(__half2*)&vaa.z);
        float2 w3 = __half22float2(*(__half2*)&vaa.w);
        acc[0] += e0 * w0.x; acc[1] += e0 * w0.y;
        acc[2] += e0 * w1.x; acc[3] += e0 * w1.y;
        acc[4] += e0 * w2.x; acc[5] += e0 * w2.y;
        acc[6] += e0 * w3.x; acc[7] += e0 * w3.y;
        float2 u0 = __half22float2(*(__half2*)&vbb.x);
        float2 u1 = __half22float2(*(__half2*)&vbb.y);
        float2 u2 = __half22float2(*(__half2*)&vbb.z);
        float2 u3 = __half22float2(*(__half2*)&vbb.w);
        acc[0] += e1 * u0.x; acc[1] += e1 * u0.y;
        acc[2] += e1 * u1.x; acc[3] += e1 * u1.y;
        acc[4] += e1 * u2.x; acc[5] += e1 * u2.y;
        acc[6] += e1 * u3.x; acc[7] += e1 * u3.y;
    }

    // merge the 8 group states (lanes differing in bits 2,3,4)
#pragma unroll
    for (int o = 4; o <= 16; o <<= 1) {
        s += __shfl_xor_sync(0xffffffffu, s, o);
#pragma unroll
        for (int j = 0; j < 8; j++)
            acc[j] += __shfl_xor_sync(0xffffffffu, acc[j], o);
    }
    if (lane < 4) {
        float inv = 1.f / s;
        float4 o0 = make_float4(acc[0] * inv, acc[1] * inv, acc[2] * inv, acc[3] * inv);
        float4 o1 = make_float4(acc[4] * inv, acc[5] * inv, acc[6] * inv, acc[7] * inv);
        *(float4*)&g_ctx[(size_t)n * DD + woff]     = o0;
        *(float4*)&g_ctx[(size_t)n * DD + woff + 4] = o1;
    }
}

// -------- warp-per-row LayerNorm + exact GELU (8 rows/block, no shared mem) --------
__global__ __launch_bounds__(256) void ln_gelu_kernel(const float* __restrict__ g,
                                                      const float* __restrict__ beta,
                                                      float* __restrict__ out) {
    int r = blockIdx.x * 8 + (threadIdx.x >> 5);
    int lane = threadIdx.x & 31;
    const float* row = g_y + (size_t)r * DD + lane * 8;
    float4 v0 = *(const float4*)row;
    float4 v1 = *(const float4*)(row + 4);

    float sum = v0.x + v0.y + v0.z + v0.w + v1.x + v1.y + v1.z + v1.w;
    float ss  = v0.x * v0.x + v0.y * v0.y + v0.z * v0.z + v0.w * v0.w
              + v1.x * v1.x + v1.y * v1.y + v1.z * v1.z + v1.w * v1.w;
#pragma unroll
    for (int o = 16; o; o >>= 1) {
        sum += __shfl_xor_sync(0xffffffffu, sum, o);
        ss  += __shfl_xor_sync(0xffffffffu, ss, o);
    }
    float mean = sum * (1.f / 256.f);
    float var  = ss * (1.f / 256.f) - mean * mean;
    float rstd = rsqrtf(var + 1e-5f);

    float4 g0 = *(const float4*)(g + lane * 8);
    float4 g1 = *(const float4*)(g + lane * 8 + 4);
    float4 b0 = *(const float4*)(beta + lane * 8);
    float4 b1 = *(const float4*)(beta + lane * 8 + 4);

    float vv[8] = {v0.x, v0.y, v0.z, v0.w, v1.x, v1.y, v1.z, v1.w};
    float gg[8] = {g0.x, g0.y, g0.z, g0.w, g1.x, g1.y, g1.z, g1.w};
    float bb[8] = {b0.x, b0.y, b0.z, b0.w, b1.x, b1.y, b1.z, b1.w};
    float oo[8];
#pragma unroll
    for (int j = 0; j < 8; j++) {
        float yv = (vv[j] - mean) * rstd * gg[j] + bb[j];
        oo[j] = 0.5f * yv * (1.f + erff(yv * 0.70710678118654752f));
    }
    float* orow = out + (size_t)r * DD + lane * 8;
    *(float4*)orow       = make_float4(oo[0], oo[1], oo[2], oo[3]);
    *(float4*)(orow + 4) = make_float4(oo[4], oo[5], oo[6], oo[7]);
}

// ------------------------------------------------------------------
extern "C" void kernel_launch(void* const* d_in, const int* in_sizes, int n_in,
                              void* d_out, int out_size) {
    const float* emb   = (const float*)d_in[0];
    const int*   ei    = (const int*)d_in[1];     // int32 (JAX default)
    const float* w_in  = (const float*)d_in[2];
    const float* b_in  = (const float*)d_in[3];
    const float* w_out = (const float*)d_in[4];
    const float* b_out = (const float*)d_in[5];
    const float* w_lin = (const float*)d_in[6];
    const float* b_lin = (const float*)d_in[7];
    const float* ln_g  = (const float*)d_in[8];
    const float* ln_b  = (const float*)d_in[9];
    float* out = (float*)d_out;

    const int ne = in_sizes[1] / 2;

    // 1. adjacency (g_adj is zero at start; compact re-zeroes it for replay)
    build_adj_kernel<<<(ne + 255) / 256, 256>>>(ei, ne);
    compact_kernel<<<NN / 8, 256>>>();

    // 2. qkv = emb @ W_in^T + b_in  -> q fp32 (g_q), k/v fp16 (g_kvh)
    gemm_kernel<0, 0, false><<<dim3(768 / BN, NN / BM), GNT>>>(emb, w_in, b_in, 768);

    // 3. sparse masked attention -> ctx [4096, 256]
    attn_kernel<<<NN, 256>>>();

    // 4. x = has_nb ? ctx @ W_out^T + b_out : emb
    gemm_kernel<1, 1, true><<<dim3(DD / BN, NN / BM), GNT>>>(emb, w_out, b_out, DD);

    // 5. y = x @ W_lin^T + b_lin
    gemm_kernel<2, 2, false><<<dim3(DD / BN, NN / BM), GNT>>>(emb, w_lin, b_lin, DD);

    // 6. LayerNorm + exact GELU -> out
    ln_gelu_kernel<<<NN / 8, 256>>>(ln_g, ln_b, out);
}

// round 15
// speedup vs baseline: 1.5076x; 1.5076x over previous
#include <cuda_runtime.h>
#include <cuda_fp16.h>
#include <mma.h>
#include <math.h>

using namespace nvcuda;

// Problem constants (fixed shapes)
#define NN 4096
#define DD 256
#define NW 128          // adjacency words per row (4096/32)
#define MAXD 512        // max neighbors kept (avg ~64 for random E=131072 graph)

// -------- static device scratch --------
__device__ unsigned g_adj[NN * NW];        // 2 MB bitmask adjacency
__device__ int      g_deg[NN];
__device__ int      g_nbr[NN * MAXD];      // 8 MB compact neighbor lists (pre-scaled *512)
__device__ float    g_q  [NN * DD];        // 4 MB  (q, fp32)
__device__ uint4    g_kvh_raw[NN * 64];    // 4 MB  (k,v as fp16: 512 halves/node)
__device__ float    g_ctx[NN * DD];        // 4 MB
__device__ float    g_x  [NN * DD];        // 4 MB
__device__ float    g_y  [NN * DD];        // 4 MB

// -------- scatter edges (symmetric, no self loops, dedup via OR); edge_index is int32 --------
__global__ void build_adj_kernel(const int* __restrict__ ei, int ne) {
    int e = blockIdx.x * blockDim.x + threadIdx.x;
    if (e >= ne) return;
    int s = ei[e];
    int d = ei[ne + e];
    if (s == d) return;
    if ((unsigned)s >= NN || (unsigned)d >= NN) return;
    atomicOr(&g_adj[s * NW + (d >> 5)], 1u << (d & 31));
    atomicOr(&g_adj[d * NW + (s >> 5)], 1u << (s & 31));
}

// -------- warp-per-row compaction (deterministic, sorted); re-zeroes g_adj for replay --------
__global__ __launch_bounds__(256) void compact_kernel() {
    int n = blockIdx.x * 8 + (threadIdx.x >> 5);
    int lane = threadIdx.x & 31;

    uint4 wv = *(uint4*)&g_adj[n * NW + lane * 4];
    *(uint4*)&g_adj[n * NW + lane * 4] = make_uint4(0u, 0u, 0u, 0u);  // reset for replay

    int c = __popc(wv.x) + __popc(wv.y) + __popc(wv.z) + __popc(wv.w);
    int x = c;
#pragma unroll
    for (int o = 1; o < 32; o <<= 1) {
        int y = __shfl_up_sync(0xffffffffu, x, o);
        if (lane >= o) x += y;
    }
    int total = __shfl_sync(0xffffffffu, x, 31);
    int base = x - c;                       // exclusive prefix

    int* dst = g_nbr + (size_t)n * MAXD;
    unsigned ws[4] = {wv.x, wv.y, wv.z, wv.w};
#pragma unroll
    for (int u = 0; u < 4; u++) {
        unsigned bits = ws[u];
        int boff = (lane * 4 + u) * 32;
        while (bits) {
            int b = __ffs(bits) - 1;
            bits &= bits - 1;
            if (base < MAXD) dst[base] = (boff + b) * 512;   // pre-scaled element offset
            base++;
        }
    }
    if (lane == 31) g_deg[n] = (total < MAXD) ? total : MAXD;
}

// ======== tf32 wmma GEMM: C[M,Nc] = A[M,K] @ B[Nc,K]^T + bias ========
// BM=64, BN=64, BK=16, 128 threads (4 warps 2x2, warp tile 32x32 = 2x2 m16n16k8),
// double-buffered smem, tf32 RN at smem store, smem-staged epilogue.
// ASEL: 0 = emb, 1 = g_ctx, 2 = g_x
// CSEL: 0 = qkv split output (q fp32 / kv fp16), 1 = g_x (+SELECT), 2 = g_y
#define BM 64
#define BN 64
#define GBK 16
#define BKP 20
#define GNT 128

struct GemmSmem {
    union {
        struct {
            float As[2][BM][BKP];   // 10240 B
            float Bs[2][BN][BKP];   // 10240 B
        } p;
        float stage[4][32][36];     // 18432 B (epilogue staging)
    };
};

template<int ASEL, int CSEL, bool SELECT>
__global__ __launch_bounds__(GNT) void gemm_kernel(const float* __restrict__ emb,
                                                   const float* __restrict__ B,
                                                   const float* __restrict__ bias,
                                                   int Nc) {
    const float* A = (ASEL == 0) ? emb : (ASEL == 1 ? (const float*)g_ctx : (const float*)g_x);
    const int K = DD;

    __shared__ GemmSmem sm;

    const int tid = threadIdx.x;
    const int w = tid >> 5, lane = tid & 31;
    const int wy = w >> 1, wx = w & 1;          // warp grid 2x2
    const int row0 = blockIdx.y * BM;
    const int col0 = blockIdx.x * BN;

    float4 ra[2], rb[2];
    auto gload = [&](int k0) {
#pragma unroll
        for (int u = 0; u < 2; u++) {
            int i = tid + u * GNT;
            int r = i >> 2, kk = (i & 3) * 4;
            ra[u] = *(const float4*)(A + (size_t)(row0 + r) * K + k0 + kk);
            rb[u] = *(const float4*)(B + (size_t)(col0 + r) * K + k0 + kk);
        }
    };
    auto sstore = [&](int buf) {
#pragma unroll
        for (int u = 0; u < 2; u++) {
            int i = tid + u * GNT;
            int r = i >> 2, kk = (i & 3) * 4;
            sm.p.As[buf][r][kk + 0] = wmma::__float_to_tf32(ra[u].x);
            sm.p.As[buf][r][kk + 1] = wmma::__float_to_tf32(ra[u].y);
            sm.p.As[buf][r][kk + 2] = wmma::__float_to_tf32(ra[u].z);
            sm.p.As[buf][r][kk + 3] = wmma::__float_to_tf32(ra[u].w);
            sm.p.Bs[buf][r][kk + 0] = wmma::__float_to_tf32(rb[u].x);
            sm.p.Bs[buf][r][kk + 1] = wmma::__float_to_tf32(rb[u].y);
            sm.p.Bs[buf][r][kk + 2] = wmma::__float_to_tf32(rb[u].z);
            sm.p.Bs[buf][r][kk + 3] = wmma::__float_to_tf32(rb[u].w);
        }
    };

    wmma::fragment<wmma::accumulator, 16, 16, 8, float> cf[2][2];
#pragma unroll
    for (int i = 0; i < 2; i++)
#pragma unroll
        for (int j = 0; j < 2; j++)
            wmma::fill_fragment(cf[i][j], 0.0f);

    gload(0);
    sstore(0);
    __syncthreads();

    const int KT = K / GBK;
    for (int kt = 0; kt < KT; kt++) {
        int buf = kt & 1;
        if (kt + 1 < KT) gload((kt + 1) * GBK);
#pragma unroll
        for (int ks = 0; ks < GBK; ks += 8) {
            wmma::fragment<wmma::matrix_a, 16, 16, 8, wmma::precision::tf32, wmma::row_major> af[2];
            wmma::fragment<wmma::matrix_b, 16, 16, 8, wmma::precision::tf32, wmma::col_major> bf[2];
#pragma unroll
            for (int i = 0; i < 2; i++)
                wmma::load_matrix_sync(af[i], &sm.p.As[buf][wy * 32 + i * 16][ks], BKP);
#pragma unroll
            for (int j = 0; j < 2; j++)
                wmma::load_matrix_sync(bf[j], &sm.p.Bs[buf][wx * 32 + j * 16][ks], BKP);
#pragma unroll
            for (int i = 0; i < 2; i++)
#pragma unroll
                for (int j = 0; j < 2; j++)
                    wmma::mma_sync(cf[i][j], af[i], bf[j], cf[i][j]);
        }
        if (kt + 1 < KT) {
            sstore(buf ^ 1);
            __syncthreads();
        }
    }

    // epilogue: stage accumulators to smem, add bias, route to destination
    __syncthreads();
#pragma unroll
    for (int i = 0; i < 2; i++)
#pragma unroll
        for (int j = 0; j < 2; j++)
            wmma::store_matrix_sync(&sm.stage[w][i * 16][j * 16], cf[i][j], 36, wmma::mem_row_major);
    __syncwarp();

    {
        int r = row0 + wy * 32 + lane;
        int cbase = col0 + wx * 32;
        bool alt = SELECT && (g_deg[r] == 0);
#pragma unroll
        for (int j = 0; j < 8; j++) {
            int cc = cbase + j * 4;
            float4 bv = *(const float4*)(bias + cc);
            float4 v;
            v.x = sm.stage[w][lane][j * 4 + 0] + bv.x;
            v.y = sm.stage[w][lane][j * 4 + 1] + bv.y;
            v.z = sm.stage[w][lane][j * 4 + 2] + bv.z;
            v.w = sm.stage[w][lane][j * 4 + 3] + bv.w;
            if (CSEL == 0) {
                if (cbase < 256) {                       // q -> fp32
                    *(float4*)(g_q + (size_t)r * DD + cc) = v;
                } else {                                 // k,v -> fp16
                    __half2 h01 = __floats2half2_rn(v.x, v.y);
                    __half2 h23 = __floats2half2_rn(v.z, v.w);
                    uint2 hv;
                    hv.x = *(unsigned*)&h01;
                    hv.y = *(unsigned*)&h23;
                    *(uint2*)((__half*)g_kvh_raw + (size_t)r * 512 + (cc - 256)) = hv;
                }
            } else {
                float* C = (CSEL == 1) ? g_x : g_y;
                if (SELECT && alt) v = *(const float4*)(emb + (size_t)r * DD + cc);
                *(float4*)(C + (size_t)r * Nc + cc) = v;
            }
        }
    }
}

// ======== sparse attention (fp16 k/v): 4-lane dot groups, 16 neighbors per warp-iter ========
// R11 configuration (best measured): block = node, 8 warps = 8 heads, smem-staged
// neighbor list, fp32 score dot, MLP=4. Lane: group g = lane>>2 (neighbor slot 0..7),
// d8 = (lane&3)*8. No online max (scores ~N(0,0.1)); exp clamp 80; exp(-inf)=0 tail.
__global__ __launch_bounds__(256) void attn_kernel() {
    __shared__ int snbr[MAXD];
    __shared__ int sdeg;
    int n = blockIdx.x, tid = threadIdx.x;
    int w = tid >> 5, lane = tid & 31;
    int g = lane >> 2, d8 = (lane & 3) * 8;
    if (tid == 0) sdeg = g_deg[n];
    __syncthreads();
    int dg = sdeg;
    for (int i = tid; i < dg; i += 256)
        snbr[i] = g_nbr[(size_t)n * MAXD + i];   // already pre-scaled *512
    __syncthreads();

    const int woff = w * 32 + d8;

    if (dg == 0) {
        if (lane < 4) {
            *(float4*)&g_ctx[(size_t)n * DD + woff]     = make_float4(0.f, 0.f, 0.f, 0.f);
            *(float4*)&g_ctx[(size_t)n * DD + woff + 4] = make_float4(0.f, 0.f, 0.f, 0.f);
        }
        return;
    }

    float q8[8];
    *(float4*)&q8[0] = *(const float4*)(g_q + (size_t)n * DD + woff);
    *(float4*)&q8[4] = *(const float4*)(g_q + (size_t)n * DD + woff + 4);

    const float sc = 0.17677669529663687f;    // 1/sqrt(32)
    float s = 0.f;
    float acc[8] = {};
    const __half* kvh = (const __half*)g_kvh_raw;

    for (int i = 0; i < dg; i += 16) {
        int idx0 = i + g, idx1 = i + 8 + g;
        bool va = idx0 < dg, vb = idx1 < dg;
        const __half* pa = kvh + snbr[va ? idx0 : i] + woff;
        const __half* pb = kvh + snbr[vb ? idx1 : i] + woff;
        uint4 ka = *(const uint4*)pa;
        uint4 kb = *(const uint4*)pb;
        uint4 vaa = *(const uint4*)(pa + 256);
        uint4 vbb = *(const uint4*)(pb + 256);

        float2 a0 = __half22float2(*(__half2*)&ka.x);
        float2 a1 = __half22float2(*(__half2*)&ka.y);
        float2 a2 = __half22float2(*(__half2*)&ka.z);
        float2 a3 = __half22float2(*(__half2*)&ka.w);
        float2 b0 = __half22float2(*(__half2*)&kb.x);
        float2 b1 = __half22float2(*(__half2*)&kb.y);
        float2 b2 = __half22float2(*(__half2*)&kb.z);
        float2 b3 = __half22float2(*(__half2*)&kb.w);

        float p0 = q8[0] * a0.x + q8[1] * a0.y + q8[2] * a1.x + q8[3] * a1.y
                 + q8[4] * a2.x + q8[5] * a2.y + q8[6] * a3.x + q8[7] * a3.y;
        float p1 = q8[0] * b0.x + q8[1] * b0.y + q8[2] * b1.x + q8[3] * b1.y
                 + q8[4] * b2.x + q8[5] * b2.y + q8[6] * b3.x + q8[7] * b3.y;
        p0 += __shfl_xor_sync(0xffffffffu, p0, 1);
        p1 += __shfl_xor_sync(0xffffffffu, p1, 1);
        p0 += __shfl_xor_sync(0xffffffffu, p0, 2);
        p1 += __shfl_xor_sync(0xffffffffu, p1, 2);
        p0 = va ? fminf(p0 * sc, 80.f) : -INFINITY;
        p1 = vb ? fminf(p1 * sc, 80.f) : -INFINITY;
        float e0 = __expf(p0);
        float e1 = __expf(p1);
        s += e0 + e1;

        float2 w0 = __half22float2(*(__half2*)&vaa.x);
        float2 w1 = __half22float2(*(__half2*)&vaa.y);
        float2 w2 = __half22float2(*(__half2*)&vaa.z);
        float2 w3 = __half22float2(*(__half2*)&vaa.w);
        acc[0] += e0 * w0.x; acc[1] += e0 * w0.y;
        acc[2] += e0 * w1.x; acc[3] += e0 * w1.y;
        acc[4] += e0 * w2.x; acc[5] += e0 * w2.y;
        acc[6] += e0 * w3.x; acc[7] += e0 * w3.y;
        float2 u0 = __half22float2(*(__half2*)&vbb.x);
        float2 u1 = __half22float2(*(__half2*)&vbb.y);
        float2 u2 = __half22float2(*(__half2*)&vbb.z);
        float2 u3 = __half22float2(*(__half2*)&vbb.w);
        acc[0] += e1 * u0.x; acc[1] += e1 * u0.y;
        acc[2] += e1 * u1.x; acc[3] += e1 * u1.y;
        acc[4] += e1 * u2.x; acc[5] += e1 * u2.y;
        acc[6] += e1 * u3.x; acc[7] += e1 * u3.y;
    }

    // merge the 8 group states (lanes differing in bits 2,3,4)
#pragma unroll
    for (int o = 4; o <= 16; o <<= 1) {
        s += __shfl_xor_sync(0xffffffffu, s, o);
#pragma unroll
        for (int j = 0; j < 8; j++)
            acc[j] += __shfl_xor_sync(0xffffffffu, acc[j], o);
    }
    if (lane < 4) {
        float inv = 1.f / s;
        float4 o0 = make_float4(acc[0] * inv, acc[1] * inv, acc[2] * inv, acc[3] * inv);
        float4 o1 = make_float4(acc[4] * inv, acc[5] * inv, acc[6] * inv, acc[7] * inv);
        *(float4*)&g_ctx[(size_t)n * DD + woff]     = o0;
        *(float4*)&g_ctx[(size_t)n * DD + woff + 4] = o1;
    }
}

// -------- warp-per-row LayerNorm + exact GELU (8 rows/block, no shared mem) --------
__global__ __launch_bounds__(256) void ln_gelu_kernel(const float* __restrict__ g,
                                                      const float* __restrict__ beta,
                                                      float* __restrict__ out) {
    int r = blockIdx.x * 8 + (threadIdx.x >> 5);
    int lane = threadIdx.x & 31;
    const float* row = g_y + (size_t)r * DD + lane * 8;
    float4 v0 = *(const float4*)row;
    float4 v1 = *(const float4*)(row + 4);

    float sum = v0.x + v0.y + v0.z + v0.w + v1.x + v1.y + v1.z + v1.w;
    float ss  = v0.x * v0.x + v0.y * v0.y + v0.z * v0.z + v0.w * v0.w
              + v1.x * v1.x + v1.y * v1.y + v1.z * v1.z + v1.w * v1.w;
#pragma unroll
    for (int o = 16; o; o >>= 1) {
        sum += __shfl_xor_sync(0xffffffffu, sum, o);
        ss  += __shfl_xor_sync(0xffffffffu, ss, o);
    }
    float mean = sum * (1.f / 256.f);
    float var  = ss * (1.f / 256.f) - mean * mean;
    float rstd = rsqrtf(var + 1e-5f);

    float4 g0 = *(const float4*)(g + lane * 8);
    float4 g1 = *(const float4*)(g + lane * 8 + 4);
    float4 b0 = *(const float4*)(beta + lane * 8);
    float4 b1 = *(const float4*)(beta + lane * 8 + 4);

    float vv[8] = {v0.x, v0.y, v0.z, v0.w, v1.x, v1.y, v1.z, v1.w};
    float gg[8] = {g0.x, g0.y, g0.z, g0.w, g1.x, g1.y, g1.z, g1.w};
    float bb[8] = {b0.x, b0.y, b0.z, b0.w, b1.x, b1.y, b1.z, b1.w};
    float oo[8];
#pragma unroll
    for (int j = 0; j < 8; j++) {
        float yv = (vv[j] - mean) * rstd * gg[j] + bb[j];
        oo[j] = 0.5f * yv * (1.f + erff(yv * 0.70710678118654752f));
    }
    float* orow = out + (size_t)r * DD + lane * 8;
    *(float4*)orow       = make_float4(oo[0], oo[1], oo[2], oo[3]);
    *(float4*)(orow + 4) = make_float4(oo[4], oo[5], oo[6], oo[7]);
}

// ------------------------------------------------------------------
extern "C" void kernel_launch(void* const* d_in, const int* in_sizes, int n_in,
                              void* d_out, int out_size) {
    const float* emb   = (const float*)d_in[0];
    const int*   ei    = (const int*)d_in[1];     // int32 (JAX default)
    const float* w_in  = (const float*)d_in[2];
    const float* b_in  = (const float*)d_in[3];
    const float* w_out = (const float*)d_in[4];
    const float* b_out = (const float*)d_in[5];
    const float* w_lin = (const float*)d_in[6];
    const float* b_lin = (const float*)d_in[7];
    const float* ln_g  = (const float*)d_in[8];
    const float* ln_b  = (const float*)d_in[9];
    float* out = (float*)d_out;

    const int ne = in_sizes[1] / 2;

    // 1. adjacency (g_adj is zero at start; compact re-zeroes it for replay)
    build_adj_kernel<<<(ne + 255) / 256, 256>>>(ei, ne);
    compact_kernel<<<NN / 8, 256>>>();

    // 2. qkv = emb @ W_in^T + b_in  -> q fp32 (g_q), k/v fp16 (g_kvh)
    gemm_kernel<0, 0, false><<<dim3(768 / BN, NN / BM), GNT>>>(emb, w_in, b_in, 768);

    // 3. sparse masked attention -> ctx [4096, 256]
    attn_kernel<<<NN, 256>>>();

    // 4. x = has_nb ? ctx @ W_out^T + b_out : emb
    gemm_kernel<1, 1, true><<<dim3(DD / BN, NN / BM), GNT>>>(emb, w_out, b_out, DD);

    // 5. y = x @ W_lin^T + b_lin
    gemm_kernel<2, 2, false><<<dim3(DD / BN, NN / BM), GNT>>>(emb, w_lin, b_lin, DD);

    // 6. LayerNorm + exact GELU -> out
    ln_gelu_kernel<<<NN / 8, 256>>>(ln_g, ln_b, out);
}

// round 16
// speedup vs baseline: 1.5360x; 1.0188x over previous
#include <cuda_runtime.h>
#include <cuda_fp16.h>
#include <mma.h>
#include <math.h>

using namespace nvcuda;

// Problem constants (fixed shapes)
#define NN 4096
#define DD 256
#define NW 128          // adjacency words per row (4096/32)
#define MAXD 512        // max neighbors kept (avg ~64 for random E=131072 graph)

// -------- static device scratch --------
__device__ unsigned g_adj[NN * NW];        // 2 MB bitmask adjacency
__device__ int      g_deg[NN];
__device__ int      g_nbr[NN * MAXD];      // 8 MB compact neighbor lists (pre-scaled *512)
__device__ float    g_q  [NN * DD];        // 4 MB  (q, fp32)
__device__ uint4    g_kvh_raw[NN * 64];    // 4 MB  (k,v as fp16: 512 halves/node)
__device__ float    g_ctx[NN * DD];        // 4 MB
__device__ float    g_y  [NN * DD];        // 4 MB
__device__ float    g_wc [DD * DD];        // 256 KB  Wc = Wlin @ Wout
__device__ float    g_bc [DD];             //         bc = Wlin·bout + blin

// -------- scatter edges (symmetric, no self loops, dedup via OR); edge_index is int32 --------
__global__ void build_adj_kernel(const int* __restrict__ ei, int ne) {
    int e = blockIdx.x * blockDim.x + threadIdx.x;
    if (e >= ne) return;
    int s = ei[e];
    int d = ei[ne + e];
    if (s == d) return;
    if ((unsigned)s >= NN || (unsigned)d >= NN) return;
    atomicOr(&g_adj[s * NW + (d >> 5)], 1u << (d & 31));
    atomicOr(&g_adj[d * NW + (s >> 5)], 1u << (s & 31));
}

// -------- warp-per-row compaction (deterministic, sorted); re-zeroes g_adj for replay --------
__global__ __launch_bounds__(256) void compact_kernel() {
    int n = blockIdx.x * 8 + (threadIdx.x >> 5);
    int lane = threadIdx.x & 31;

    uint4 wv = *(uint4*)&g_adj[n * NW + lane * 4];
    *(uint4*)&g_adj[n * NW + lane * 4] = make_uint4(0u, 0u, 0u, 0u);  // reset for replay

    int c = __popc(wv.x) + __popc(wv.y) + __popc(wv.z) + __popc(wv.w);
    int x = c;
#pragma unroll
    for (int o = 1; o < 32; o <<= 1) {
        int y = __shfl_up_sync(0xffffffffu, x, o);
        if (lane >= o) x += y;
    }
    int total = __shfl_sync(0xffffffffu, x, 31);
    int base = x - c;                       // exclusive prefix

    int* dst = g_nbr + (size_t)n * MAXD;
    unsigned ws[4] = {wv.x, wv.y, wv.z, wv.w};
#pragma unroll
    for (int u = 0; u < 4; u++) {
        unsigned bits = ws[u];
        int boff = (lane * 4 + u) * 32;
        while (bits) {
            int b = __ffs(bits) - 1;
            bits &= bits - 1;
            if (base < MAXD) dst[base] = (boff + b) * 512;   // pre-scaled element offset
            base++;
        }
    }
    if (lane == 31) g_deg[n] = (total < MAXD) ? total : MAXD;
}

// ======== combine: Wc = Wlin @ Wout (tf32 wmma), bc = Wlin·bout + blin (fp32) ========
// Wc[i][k] = sum_m Wlin[i][m] * Wout[m][k].  BM=64 (i), BN=64 (k), BK=16 (m),
// 128 threads (4 warps 2x2, warp tile 32x32). A row-major, B ROW-major fragments.
__global__ __launch_bounds__(128) void combine_kernel(const float* __restrict__ wlin,
                                                      const float* __restrict__ wout,
                                                      const float* __restrict__ bout,
                                                      const float* __restrict__ blin) {
    __shared__ union {
        struct {
            float As[2][64][20];   // [i][m]  10240 B
            float Bs[2][16][68];   // [m][k]   8704 B
        } p;
        float stage[4][32][36];    // 18432 B
    } sm;

    const int tid = threadIdx.x;
    const int w = tid >> 5, lane = tid & 31;
    const int wy = w >> 1, wx = w & 1;
    const int i0 = blockIdx.y * 64;
    const int k0 = blockIdx.x * 64;

    float4 ra[2], rb[2];
    auto gload = [&](int m0) {
#pragma unroll
        for (int u = 0; u < 2; u++) {
            int idx = tid + u * 128;
            ra[u] = *(const float4*)(wlin + (size_t)(i0 + (idx >> 2)) * DD + m0 + (idx & 3) * 4);
            rb[u] = *(const float4*)(wout + (size_t)(m0 + (idx >> 4)) * DD + k0 + (idx & 15) * 4);
        }
    };
    auto sstore = [&](int buf) {
#pragma unroll
        for (int u = 0; u < 2; u++) {
            int idx = tid + u * 128;
            int r = idx >> 2, mc = (idx & 3) * 4;
            sm.p.As[buf][r][mc + 0] = wmma::__float_to_tf32(ra[u].x);
            sm.p.As[buf][r][mc + 1] = wmma::__float_to_tf32(ra[u].y);
            sm.p.As[buf][r][mc + 2] = wmma::__float_to_tf32(ra[u].z);
            sm.p.As[buf][r][mc + 3] = wmma::__float_to_tf32(ra[u].w);
            int m = idx >> 4, kc = (idx & 15) * 4;
            sm.p.Bs[buf][m][kc + 0] = wmma::__float_to_tf32(rb[u].x);
            sm.p.Bs[buf][m][kc + 1] = wmma::__float_to_tf32(rb[u].y);
            sm.p.Bs[buf][m][kc + 2] = wmma::__float_to_tf32(rb[u].z);
            sm.p.Bs[buf][m][kc + 3] = wmma::__float_to_tf32(rb[u].w);
        }
    };

    wmma::fragment<wmma::accumulator, 16, 16, 8, float> cf[2][2];
#pragma unroll
    for (int i = 0; i < 2; i++)
#pragma unroll
        for (int j = 0; j < 2; j++)
            wmma::fill_fragment(cf[i][j], 0.0f);

    gload(0);
    sstore(0);
    __syncthreads();

    const int MT = DD / 16;
    for (int mt = 0; mt < MT; mt++) {
        int buf = mt & 1;
        if (mt + 1 < MT) gload((mt + 1) * 16);
#pragma unroll
        for (int ks = 0; ks < 16; ks += 8) {
            wmma::fragment<wmma::matrix_a, 16, 16, 8, wmma::precision::tf32, wmma::row_major> af[2];
            wmma::fragment<wmma::matrix_b, 16, 16, 8, wmma::precision::tf32, wmma::row_major> bf[2];
#pragma unroll
            for (int i = 0; i < 2; i++)
                wmma::load_matrix_sync(af[i], &sm.p.As[buf][wy * 32 + i * 16][ks], 20);
#pragma unroll
            for (int j = 0; j < 2; j++)
                wmma::load_matrix_sync(bf[j], &sm.p.Bs[buf][ks][wx * 32 + j * 16], 68);
#pragma unroll
            for (int i = 0; i < 2; i++)
#pragma unroll
                for (int j = 0; j < 2; j++)
                    wmma::mma_sync(cf[i][j], af[i], bf[j], cf[i][j]);
        }
        if (mt + 1 < MT) {
            sstore(buf ^ 1);
            __syncthreads();
        }
    }

    __syncthreads();
#pragma unroll
    for (int i = 0; i < 2; i++)
#pragma unroll
        for (int j = 0; j < 2; j++)
            wmma::store_matrix_sync(&sm.stage[w][i * 16][j * 16], cf[i][j], 36, wmma::mem_row_major);
    __syncwarp();

    {
        int r = i0 + wy * 32 + lane;
        int cbase = k0 + wx * 32;
#pragma unroll
        for (int j = 0; j < 8; j++)
            *(float4*)(g_wc + (size_t)r * DD + cbase + j * 4) =
                *(float4*)&sm.stage[w][lane][j * 4];
    }

    // bc (fp32): blocks with bx==0, threads 0..63 each compute one row of bc
    if (blockIdx.x == 0 && tid < 64) {
        int i = i0 + tid;
        float acc = blin[i];
        const float* row = wlin + (size_t)i * DD;
#pragma unroll 8
        for (int m = 0; m < DD; m += 4) {
            float4 wv = *(const float4*)(row + m);
            float4 bv = *(const float4*)(bout + m);
            acc += wv.x * bv.x + wv.y * bv.y + wv.z * bv.z + wv.w * bv.w;
        }
        g_bc[i] = acc;
    }
}

// ======== tf32 wmma GEMM: C[M,Nc] = A[M,K] @ B[Nc,K]^T + bias ========
// BM=64, BN=64, BK=16, 128 threads (4 warps 2x2, warp tile 32x32).
// ASEL: 0 = emb, 1 = g_ctx
// CSEL: 0 = qkv split output (q fp32 / kv fp16), 2 = g_y with B=g_wc, bias=g_bc
#define BM 64
#define BN 64
#define GBK 16
#define BKP 20
#define GNT 128

struct GemmSmem {
    union {
        struct {
            float As[2][BM][BKP];   // 10240 B
            float Bs[2][BN][BKP];   // 10240 B
        } p;
        float stage[4][32][36];     // 18432 B (epilogue staging)
    };
};

template<int ASEL, int CSEL>
__global__ __launch_bounds__(GNT) void gemm_kernel(const float* __restrict__ emb,
                                                   const float* __restrict__ Barg,
                                                   const float* __restrict__ biasarg,
                                                   int Nc) {
    const float* A = (ASEL == 0) ? emb : (const float*)g_ctx;
    const float* B = (CSEL == 2) ? (const float*)g_wc : Barg;
    const float* bias = (CSEL == 2) ? (const float*)g_bc : biasarg;
    const int K = DD;

    __shared__ GemmSmem sm;

    const int tid = threadIdx.x;
    const int w = tid >> 5, lane = tid & 31;
    const int wy = w >> 1, wx = w & 1;          // warp grid 2x2
    const int row0 = blockIdx.y * BM;
    const int col0 = blockIdx.x * BN;

    float4 ra[2], rb[2];
    auto gload = [&](int k0) {
#pragma unroll
        for (int u = 0; u < 2; u++) {
            int i = tid + u * GNT;
            int r = i >> 2, kk = (i & 3) * 4;
            ra[u] = *(const float4*)(A + (size_t)(row0 + r) * K + k0 + kk);
            rb[u] = *(const float4*)(B + (size_t)(col0 + r) * K + k0 + kk);
        }
    };
    auto sstore = [&](int buf) {
#pragma unroll
        for (int u = 0; u < 2; u++) {
            int i = tid + u * GNT;
            int r = i >> 2, kk = (i & 3) * 4;
            sm.p.As[buf][r][kk + 0] = wmma::__float_to_tf32(ra[u].x);
            sm.p.As[buf][r][kk + 1] = wmma::__float_to_tf32(ra[u].y);
            sm.p.As[buf][r][kk + 2] = wmma::__float_to_tf32(ra[u].z);
            sm.p.As[buf][r][kk + 3] = wmma::__float_to_tf32(ra[u].w);
            sm.p.Bs[buf][r][kk + 0] = wmma::__float_to_tf32(rb[u].x);
            sm.p.Bs[buf][r][kk + 1] = wmma::__float_to_tf32(rb[u].y);
            sm.p.Bs[buf][r][kk + 2] = wmma::__float_to_tf32(rb[u].z);
            sm.p.Bs[buf][r][kk + 3] = wmma::__float_to_tf32(rb[u].w);
        }
    };

    wmma::fragment<wmma::accumulator, 16, 16, 8, float> cf[2][2];
#pragma unroll
    for (int i = 0; i < 2; i++)
#pragma unroll
        for (int j = 0; j < 2; j++)
            wmma::fill_fragment(cf[i][j], 0.0f);

    gload(0);
    sstore(0);
    __syncthreads();

    const int KT = K / GBK;
    for (int kt = 0; kt < KT; kt++) {
        int buf = kt & 1;
        if (kt + 1 < KT) gload((kt + 1) * GBK);
#pragma unroll
        for (int ks = 0; ks < GBK; ks += 8) {
            wmma::fragment<wmma::matrix_a, 16, 16, 8, wmma::precision::tf32, wmma::row_major> af[2];
            wmma::fragment<wmma::matrix_b, 16, 16, 8, wmma::precision::tf32, wmma::col_major> bf[2];
#pragma unroll
            for (int i = 0; i < 2; i++)
                wmma::load_matrix_sync(af[i], &sm.p.As[buf][wy * 32 + i * 16][ks], BKP);
#pragma unroll
            for (int j = 0; j < 2; j++)
                wmma::load_matrix_sync(bf[j], &sm.p.Bs[buf][wx * 32 + j * 16][ks], BKP);
#pragma unroll
            for (int i = 0; i < 2; i++)
#pragma unroll
                for (int j = 0; j < 2; j++)
                    wmma::mma_sync(cf[i][j], af[i], bf[j], cf[i][j]);
        }
        if (kt + 1 < KT) {
            sstore(buf ^ 1);
            __syncthreads();
        }
    }

    // epilogue: stage accumulators to smem, add bias, route to destination
    __syncthreads();
#pragma unroll
    for (int i = 0; i < 2; i++)
#pragma unroll
        for (int j = 0; j < 2; j++)
            wmma::store_matrix_sync(&sm.stage[w][i * 16][j * 16], cf[i][j], 36, wmma::mem_row_major);
    __syncwarp();

    {
        int r = row0 + wy * 32 + lane;
        int cbase = col0 + wx * 32;
#pragma unroll
        for (int j = 0; j < 8; j++) {
            int cc = cbase + j * 4;
            float4 bv = *(const float4*)(bias + cc);
            float4 v;
            v.x = sm.stage[w][lane][j * 4 + 0] + bv.x;
            v.y = sm.stage[w][lane][j * 4 + 1] + bv.y;
            v.z = sm.stage[w][lane][j * 4 + 2] + bv.z;
            v.w = sm.stage[w][lane][j * 4 + 3] + bv.w;
            if (CSEL == 0) {
                if (cbase < 256) {                       // q -> fp32
                    *(float4*)(g_q + (size_t)r * DD + cc) = v;
                } else {                                 // k,v -> fp16
                    __half2 h01 = __floats2half2_rn(v.x, v.y);
                    __half2 h23 = __floats2half2_rn(v.z, v.w);
                    uint2 hv;
                    hv.x = *(unsigned*)&h01;
                    hv.y = *(unsigned*)&h23;
                    *(uint2*)((__half*)g_kvh_raw + (size_t)r * 512 + (cc - 256)) = hv;
                }
            } else {
                *(float4*)(g_y + (size_t)r * Nc + cc) = v;
            }
        }
    }
}

// ======== sparse attention (fp16 k/v): 4-lane dot groups, 16 neighbors per warp-iter ========
// R11 configuration (best measured): block = node, 8 warps = 8 heads, smem-staged
// neighbor list, fp32 score dot, MLP=4. No online max (scores ~N(0,0.1)).
__global__ __launch_bounds__(256) void attn_kernel() {
    __shared__ int snbr[MAXD];
    __shared__ int sdeg;
    int n = blockIdx.x, tid = threadIdx.x;
    int w = tid >> 5, lane = tid & 31;
    int g = lane >> 2, d8 = (lane & 3) * 8;
    if (tid == 0) sdeg = g_deg[n];
    __syncthreads();
    int dg = sdeg;
    for (int i = tid; i < dg; i += 256)
        snbr[i] = g_nbr[(size_t)n * MAXD + i];   // already pre-scaled *512
    __syncthreads();

    const int woff = w * 32 + d8;

    if (dg == 0) {
        if (lane < 4) {
            *(float4*)&g_ctx[(size_t)n * DD + woff]     = make_float4(0.f, 0.f, 0.f, 0.f);
            *(float4*)&g_ctx[(size_t)n * DD + woff + 4] = make_float4(0.f, 0.f, 0.f, 0.f);
        }
        return;
    }

    float q8[8];
    *(float4*)&q8[0] = *(const float4*)(g_q + (size_t)n * DD + woff);
    *(float4*)&q8[4] = *(const float4*)(g_q + (size_t)n * DD + woff + 4);

    const float sc = 0.17677669529663687f;    // 1/sqrt(32)
    float s = 0.f;
    float acc[8] = {};
    const __half* kvh = (const __half*)g_kvh_raw;

    for (int i = 0; i < dg; i += 16) {
        int idx0 = i + g, idx1 = i + 8 + g;
        bool va = idx0 < dg, vb = idx1 < dg;
        const __half* pa = kvh + snbr[va ? idx0 : i] + woff;
        const __half* pb = kvh + snbr[vb ? idx1 : i] + woff;
        uint4 ka = *(const uint4*)pa;
        uint4 kb = *(const uint4*)pb;
        uint4 vaa = *(const uint4*)(pa + 256);
        uint4 vbb = *(const uint4*)(pb + 256);

        float2 a0 = __half22float2(*(__half2*)&ka.x);
        float2 a1 = __half22float2(*(__half2*)&ka.y);
        float2 a2 = __half22float2(*(__half2*)&ka.z);
        float2 a3 = __half22float2(*(__half2*)&ka.w);
        float2 b0 = __half22float2(*(__half2*)&kb.x);
        float2 b1 = __half22float2(*(__half2*)&kb.y);
        float2 b2 = __half22float2(*(__half2*)&kb.z);
        float2 b3 = __half22float2(*(__half2*)&kb.w);

        float p0 = q8[0] * a0.x + q8[1] * a0.y + q8[2] * a1.x + q8[3] * a1.y
                 + q8[4] * a2.x + q8[5] * a2.y + q8[6] * a3.x + q8[7] * a3.y;
        float p1 = q8[0] * b0.x + q8[1] * b0.y + q8[2] * b1.x + q8[3] * b1.y
                 + q8[4] * b2.x + q8[5] * b2.y + q8[6] * b3.x + q8[7] * b3.y;
        p0 += __shfl_xor_sync(0xffffffffu, p0, 1);
        p1 += __shfl_xor_sync(0xffffffffu, p1, 1);
        p0 += __shfl_xor_sync(0xffffffffu, p0, 2);
        p1 += __shfl_xor_sync(0xffffffffu, p1, 2);
        p0 = va ? fminf(p0 * sc, 80.f) : -INFINITY;
        p1 = vb ? fminf(p1 * sc, 80.f) : -INFINITY;
        float e0 = __expf(p0);
        float e1 = __expf(p1);
        s += e0 + e1;

        float2 w0 = __half22float2(*(__half2*)&vaa.x);
        float2 w1 = __half22float2(*(__half2*)&vaa.y);
        float2 w2 = __half22float2(*(__half2*)&vaa.z);
        float2 w3 = __half22float2(*(__half2*)&vaa.w);
        acc[0] += e0 * w0.x; acc[1] += e0 * w0.y;
        acc[2] += e0 * w1.x; acc[3] += e0 * w1.y;
        acc[4] += e0 * w2.x; acc[5] += e0 * w2.y;
        acc[6] += e0 * w3.x; acc[7] += e0 * w3.y;
        float2 u0 = __half22float2(*(__half2*)&vbb.x);
        float2 u1 = __half22float2(*(__half2*)&vbb.y);
        float2 u2 = __half22float2(*(__half2*)&vbb.z);
        float2 u3 = __half22float2(*(__half2*)&vbb.w);
        acc[0] += e1 * u0.x; acc[1] += e1 * u0.y;
        acc[2] += e1 * u1.x; acc[3] += e1 * u1.y;
        acc[4] += e1 * u2.x; acc[5] += e1 * u2.y;
        acc[6] += e1 * u3.x; acc[7] += e1 * u3.y;
    }

    // merge the 8 group states (lanes differing in bits 2,3,4)
#pragma unroll
    for (int o = 4; o <= 16; o <<= 1) {
        s += __shfl_xor_sync(0xffffffffu, s, o);
#pragma unroll
        for (int j = 0; j < 8; j++)
            acc[j] += __shfl_xor_sync(0xffffffffu, acc[j], o);
    }
    if (lane < 4) {
        float inv = 1.f / s;
        float4 o0 = make_float4(acc[0] * inv, acc[1] * inv, acc[2] * inv, acc[3] * inv);
        float4 o1 = make_float4(acc[4] * inv, acc[5] * inv, acc[6] * inv, acc[7] * inv);
        *(float4*)&g_ctx[(size_t)n * DD + woff]     = o0;
        *(float4*)&g_ctx[(size_t)n * DD + woff + 4] = o1;
    }
}

// -------- warp-per-row LayerNorm + exact GELU; deg==0 rows take y = emb@Wlin^T + blin --------
__global__ __launch_bounds__(256) void ln_gelu_kernel(const float* __restrict__ g,
                                                      const float* __restrict__ beta,
                                                      const float* __restrict__ emb,
                                                      const float* __restrict__ wlin,
                                                      const float* __restrict__ blin,
                                                      float* __restrict__ out) {
    int r = blockIdx.x * 8 + (threadIdx.x >> 5);
    int lane = threadIdx.x & 31;

    float vv[8];
    if (g_deg[r] != 0) {
        const float* row = g_y + (size_t)r * DD + lane * 8;
        *(float4*)&vv[0] = *(const float4*)row;
        *(float4*)&vv[4] = *(const float4*)(row + 4);
    } else {
        // rare path (P ~ e^-64): y = emb[r] @ Wlin^T + blin, fp32 (warp-uniform branch)
        const float* er = emb + (size_t)r * DD;
#pragma unroll
        for (int j = 0; j < 8; j++) {
            int c = lane * 8 + j;
            float a = blin[c];
            const float* wr = wlin + (size_t)c * DD;
            for (int m = 0; m < DD; m += 4) {
                float4 wv = *(const float4*)(wr + m);
                float4 ev = *(const float4*)(er + m);
                a += wv.x * ev.x + wv.y * ev.y + wv.z * ev.z + wv.w * ev.w;
            }
            vv[j] = a;
        }
    }

    float sum = 0.f, ss = 0.f;
#pragma unroll
    for (int j = 0; j < 8; j++) { sum += vv[j]; ss += vv[j] * vv[j]; }
#pragma unroll
    for (int o = 16; o; o >>= 1) {
        sum += __shfl_xor_sync(0xffffffffu, sum, o);
        ss  += __shfl_xor_sync(0xffffffffu, ss, o);
    }
    float mean = sum * (1.f / 256.f);
    float var  = ss * (1.f / 256.f) - mean * mean;
    float rstd = rsqrtf(var + 1e-5f);

    float4 g0 = *(const float4*)(g + lane * 8);
    float4 g1 = *(const float4*)(g + lane * 8 + 4);
    float4 b0 = *(const float4*)(beta + lane * 8);
    float4 b1 = *(const float4*)(beta + lane * 8 + 4);

    float gg[8] = {g0.x, g0.y, g0.z, g0.w, g1.x, g1.y, g1.z, g1.w};
    float bb[8] = {b0.x, b0.y, b0.z, b0.w, b1.x, b1.y, b1.z, b1.w};
    float oo[8];
#pragma unroll
    for (int j = 0; j < 8; j++) {
        float yv = (vv[j] - mean) * rstd * gg[j] + bb[j];
        oo[j] = 0.5f * yv * (1.f + erff(yv * 0.70710678118654752f));
    }
    float* orow = out + (size_t)r * DD + lane * 8;
    *(float4*)orow       = make_float4(oo[0], oo[1], oo[2], oo[3]);
    *(float4*)(orow + 4) = make_float4(oo[4], oo[5], oo[6], oo[7]);
}

// ------------------------------------------------------------------
extern "C" void kernel_launch(void* const* d_in, const int* in_sizes, int n_in,
                              void* d_out, int out_size) {
    const float* emb   = (const float*)d_in[0];
    const int*   ei    = (const int*)d_in[1];     // int32 (JAX default)
    const float* w_in  = (const float*)d_in[2];
    const float* b_in  = (const float*)d_in[3];
    const float* w_out = (const float*)d_in[4];
    const float* b_out = (const float*)d_in[5];
    const float* w_lin = (const float*)d_in[6];
    const float* b_lin = (const float*)d_in[7];
    const float* ln_g  = (const float*)d_in[8];
    const float* ln_b  = (const float*)d_in[9];
    float* out = (float*)d_out;

    const int ne = in_sizes[1] / 2;

    // 1. adjacency (g_adj is zero at start; compact re-zeroes it for replay)
    build_adj_kernel<<<(ne + 255) / 256, 256>>>(ei, ne);
    compact_kernel<<<NN / 8, 256>>>();

    // 2. qkv = emb @ W_in^T + b_in  -> q fp32 (g_q), k/v fp16 (g_kvh)
    gemm_kernel<0, 0><<<dim3(768 / BN, NN / BM), GNT>>>(emb, w_in, b_in, 768);

    // 3. sparse masked attention -> ctx [4096, 256]
    attn_kernel<<<NN, 256>>>();

    // 4. combined weight Wc = Wlin @ Wout, bc = Wlin·bout + blin  (tf32 wmma, 1 wave)
    combine_kernel<<<dim3(4, 4), 128>>>(w_lin, w_out, b_out, b_lin);

    // 5. y = ctx @ Wc^T + bc   (fused out-proj + lin)
    gemm_kernel<1, 2><<<dim3(DD / BN, NN / BM), GNT>>>(emb, nullptr, nullptr, DD);

    // 6. LayerNorm + exact GELU -> out (deg==0 rows fixed up inline)
    ln_gelu_kernel<<<NN / 8, 256>>>(ln_g, ln_b, emb, w_lin, b_lin, out);
}